// round 9
// baseline (speedup 1.0000x reference)
#include <cuda_runtime.h>
#include <stdint.h>

typedef unsigned long long ull;

#define DD     1024
#define LLEN   2048
#define KK     32
#define KHALF  16
#define NSLOT  8            // 16 poles per lane, packed in pairs
#define QLEN   512          // time-quarter per warp
#define SREC   16           // recurrence stride
#define STEPS  (QLEN / SREC)    // 32 steps

// ---- packed f32x2 helpers (sm_100+ PTX; ptxas never emits these from C++) ----
__device__ __forceinline__ ull f2pack(float lo, float hi) {
    ull r;
    asm("mov.b64 %0, {%1, %2};" : "=l"(r) : "r"(__float_as_uint(lo)), "r"(__float_as_uint(hi)));
    return r;
}
__device__ __forceinline__ void f2unpack(ull v, float& lo, float& hi) {
    unsigned a, b;
    asm("mov.b64 {%0, %1}, %2;" : "=r"(a), "=r"(b) : "l"(v));
    lo = __uint_as_float(a);
    hi = __uint_as_float(b);
}
__device__ __forceinline__ ull f2add(ull a, ull b) {
    ull d; asm("add.rn.f32x2 %0, %1, %2;" : "=l"(d) : "l"(a), "l"(b)); return d;
}
__device__ __forceinline__ ull f2mul(ull a, ull b) {
    ull d; asm("mul.rn.f32x2 %0, %1, %2;" : "=l"(d) : "l"(a), "l"(b)); return d;
}
__device__ __forceinline__ ull f2fma(ull a, ull b, ull c) {
    ull d; asm("fma.rn.f32x2 %0, %1, %2, %3;" : "=l"(d) : "l"(a), "l"(b), "l"(c)); return d;
}

__device__ __forceinline__ float reduce8(const ull* x) {
    ull c0 = f2add(x[0], x[1]);  c0 = f2add(c0, x[2]);  c0 = f2add(c0, x[3]);
    ull c1 = f2add(x[4], x[5]);  c1 = f2add(c1, x[6]);  c1 = f2add(c1, x[7]);
    ull t  = f2add(c0, c1);
    float lo, hi;
    f2unpack(t, lo, hi);
    return lo + hi;
}

// x_k[t] = Re(R_k p_k^t) obeys the stride-16 real recurrence
//   x[t] = A_k x[t-16] + B_k x[t-32],  A_k = 2 r^16 cos(16 th),  B_k = -r^32.
// CTA = 128 threads = one row d. Warp = time-quarter (512 values of t).
// Lane = (kh = lane>>4 pole-half, tsub = lane&15 time offset). Cross-k merge is
// one shfl.xor(16) + add. Stage 1 (threads 0..31) computes per-k transcendentals
// once per CTA into smem; stage 2 loads them (hoistable, B stays in registers).
// launch_bounds(128,7) caps regs at 73 -> 28 resident warps/SM -> single wave.
__global__ void __launch_bounds__(128, 7) modal_kernel(
    const float* __restrict__ rr, const float* __restrict__ th,
    const float* __restrict__ Rre, const float* __restrict__ Rim,
    const float* __restrict__ h0, float* __restrict__ out)
{
    __shared__ float sh_lr[KK], sh_r16[KK], sh_s16[KK], sh_c16[KK], sh_th[KK];
    __shared__ float sh_B[KK];

    const int tid     = threadIdx.x;
    const int lane    = tid & 31;
    const int quarter = tid >> 5;
    const int d       = blockIdx.x;
    const int tsub    = lane & 15;
    const int kh      = lane >> 4;

    const float INV2PI = 0.15915494309189535f;
    const float PI2_HI = 6.2831854820251465f;   // fp32(2*pi)
    const float PI2_LO = -1.7484555e-7f;        // 2*pi - PI2_HI

    // ---- stage 1: per-k shared setup (threads 0..31, one k each) ----
    if (tid < KK) {
        const int off = tid * DD + d;
        float rk = __ldg(rr + off);
        float tk = __ldg(th + off);
        float lr = __logf(rk);
        float r2 = rk * rk, r4 = r2 * r2, r8 = r4 * r4, r16 = r8 * r8;
        float qa = 16.0f * tk;                  // exact (power-of-two scale)
        float nq = rintf(qa * INV2PI);
        qa = fmaf(-nq, PI2_HI, qa);
        qa = fmaf(-nq, PI2_LO, qa);
        float s16, c16;
        __sincosf(qa, &s16, &c16);
        sh_lr[tid]  = lr;
        sh_r16[tid] = r16;
        sh_s16[tid] = s16;
        sh_c16[tid] = c16;
        sh_th[tid]  = tk;
        sh_B[tid]   = -r16 * r16;
    }
    __syncthreads();

    // ---- stage 2: per-thread seeds; A and B packed in registers ----
    ull x1[NSLOT], x2[NSLOT], A[NSLOT], B[NSLOT];

    // seed exponents: e1 = quarter*512 + tsub - 1 (first output), e2 = e1 - 16
    const float t2f = (float)(quarter * QLEN + tsub - 17);

    float p_x1 = 0.f, p_x2 = 0.f, p_A = 0.f, p_B = 0.f;

#pragma unroll
    for (int kk = 0; kk < KHALF; ++kk) {
        const int k = kh * KHALF + kk;
        float lr  = sh_lr[k];
        float r16 = sh_r16[k];
        float s16 = sh_s16[k];
        float c16 = sh_c16[k];
        float tk  = sh_th[k];
        float cB  = sh_B[k];
        const int off = k * DD + d;
        float ar = __ldg(Rre + off);
        float ai = __ldg(Rim + off);

        float cA = 2.0f * r16 * c16;

        // seed x2 = x(e2): phase e2*th via exact twoProd + 2-term Cody-Waite
        float radm = __expf(t2f * lr);
        float ph = t2f * tk;
        float pe = fmaf(t2f, tk, -ph);          // exact low part of the product
        float n2 = rintf(ph * INV2PI);
        float a2 = fmaf(-n2, PI2_HI, ph);
        a2 = a2 + pe;
        a2 = fmaf(-n2, PI2_LO, a2);
        float sm, cm;
        __sincosf(a2, &sm, &cm);
        float cx2 = radm * (ar * cm - ai * sm);

        // seed x1 = x(e2+16): rotate phase by 16 th, scale radius by r^16
        float rad0 = radm * r16;
        float c0 = cm * c16 - sm * s16;
        float s0 = sm * c16 + cm * s16;
        float cx1 = rad0 * (ar * c0 - ai * s0);

        if (kk & 1) {
            x1[kk >> 1] = f2pack(p_x1, cx1);
            x2[kk >> 1] = f2pack(p_x2, cx2);
            A [kk >> 1] = f2pack(p_A,  cA);
            B [kk >> 1] = f2pack(p_B,  cB);
        } else {
            p_x1 = cx1; p_x2 = cx2; p_A = cA; p_B = cB;
        }
    }

    float* outp = out + (size_t)d * LLEN + quarter * QLEN + tsub;
    const bool do_store = (kh == 0);

    // 2-step unrolled main loop; x1/x2 swap roles (no register moves)
#pragma unroll 1
    for (int i = 0; i < STEPS; i += 2) {
        {
            float part = reduce8(x1);
            float sum = part + __shfl_xor_sync(0xffffffffu, part, 16);
            if (do_store) outp[i * SREC] = sum;
        }
#pragma unroll
        for (int s = 0; s < NSLOT; ++s)
            x2[s] = f2fma(A[s], x1[s], f2mul(B[s], x2[s]));
        {
            float part = reduce8(x2);
            float sum = part + __shfl_xor_sync(0xffffffffu, part, 16);
            if (do_store) outp[(i + 1) * SREC] = sum;
        }
#pragma unroll
        for (int s = 0; s < NSLOT; ++s)
            x1[s] = f2fma(A[s], x2[s], f2mul(B[s], x1[s]));
    }

    // l == 0 carries h_0; same thread (quarter 0, lane 0) wrote l=0 above
    if (quarter == 0 && lane == 0) {
        out[(size_t)d * LLEN] = __ldg(h0 + d);
    }
}

extern "C" void kernel_launch(void* const* d_in, const int* in_sizes, int n_in,
                              void* d_out, int out_size) {
    const float* rr  = (const float*)d_in[0];
    const float* th  = (const float*)d_in[1];
    const float* Rre = (const float*)d_in[2];
    const float* Rim = (const float*)d_in[3];
    const float* h0  = (const float*)d_in[4];
    float* out = (float*)d_out;
    modal_kernel<<<DD, 128>>>(rr, th, Rre, Rim, h0, out);
}

// round 10
// speedup vs baseline: 1.1459x; 1.1459x over previous
#include <cuda_runtime.h>
#include <stdint.h>

typedef unsigned long long ull;

#define DD     1024
#define LLEN   2048
#define KK     32
#define KQ     8            // poles per lane (4-way k-split)
#define NSLOT  4            // 8 poles per lane, packed in pairs
#define SEG    512          // time-segment per warp
#define SREC   8            // recurrence stride
#define STEPS  (SEG / SREC)     // 64 steps

// ---- packed f32x2 helpers (sm_100+ PTX; ptxas never emits these from C++) ----
__device__ __forceinline__ ull f2pack(float lo, float hi) {
    ull r;
    asm("mov.b64 %0, {%1, %2};" : "=l"(r) : "r"(__float_as_uint(lo)), "r"(__float_as_uint(hi)));
    return r;
}
__device__ __forceinline__ void f2unpack(ull v, float& lo, float& hi) {
    unsigned a, b;
    asm("mov.b64 {%0, %1}, %2;" : "=r"(a), "=r"(b) : "l"(v));
    lo = __uint_as_float(a);
    hi = __uint_as_float(b);
}
__device__ __forceinline__ ull f2add(ull a, ull b) {
    ull d; asm("add.rn.f32x2 %0, %1, %2;" : "=l"(d) : "l"(a), "l"(b)); return d;
}
__device__ __forceinline__ ull f2mul(ull a, ull b) {
    ull d; asm("mul.rn.f32x2 %0, %1, %2;" : "=l"(d) : "l"(a), "l"(b)); return d;
}
__device__ __forceinline__ ull f2fma(ull a, ull b, ull c) {
    ull d; asm("fma.rn.f32x2 %0, %1, %2, %3;" : "=l"(d) : "l"(a), "l"(b), "l"(c)); return d;
}

__device__ __forceinline__ float reduce4(const ull* x) {
    ull c0 = f2add(x[0], x[1]);
    ull c1 = f2add(x[2], x[3]);
    ull t  = f2add(c0, c1);
    float lo, hi;
    f2unpack(t, lo, hi);
    return lo + hi;
}

// x_k[t] = Re(R_k p_k^t) obeys the stride-8 real recurrence
//   x[t] = A_k x[t-8] + B_k x[t-16],  A_k = 2 r^8 cos(8 th),  B_k = -r^16.
// CTA = 128 threads = one row d; warp = one 512-long time segment.
// Lane = (kq = lane>>3 pole-quarter of 8 poles, tsub = lane&7 time offset).
// Step i, lane (kq,tsub): partial sum over its 8 poles at exponent
// seg*512 + 8i + tsub - 1. Merge: shfl.xor(8)+add then shfl.xor(16)+add;
// lanes < 8 store t = seg*512 + 8i + tsub. Stage 1 (threads 0..31) computes
// per-k transcendentals once per CTA into smem.
__global__ void __launch_bounds__(128, 8) modal_kernel(
    const float* __restrict__ rr, const float* __restrict__ th,
    const float* __restrict__ Rre, const float* __restrict__ Rim,
    const float* __restrict__ h0, float* __restrict__ out)
{
    __shared__ float sh_lr[KK], sh_r8[KK], sh_s8[KK], sh_c8[KK], sh_th[KK], sh_B[KK];

    const int tid  = threadIdx.x;
    const int lane = tid & 31;
    const int seg  = tid >> 5;              // 4 warps = 4 time segments
    const int d    = blockIdx.x;
    const int tsub = lane & 7;
    const int kq   = lane >> 3;

    const float INV2PI = 0.15915494309189535f;
    const float PI2_HI = 6.2831854820251465f;   // fp32(2*pi)
    const float PI2_LO = -1.7484555e-7f;        // 2*pi - PI2_HI

    // ---- stage 1: per-k shared setup (threads 0..31, one k each) ----
    if (tid < KK) {
        const int off = tid * DD + d;
        float rk = __ldg(rr + off);
        float tk = __ldg(th + off);
        float lr = __logf(rk);
        float r2 = rk * rk, r4 = r2 * r2, r8 = r4 * r4;
        float qa = 8.0f * tk;               // exact (power-of-two scale)
        float nq = rintf(qa * INV2PI);
        qa = fmaf(-nq, PI2_HI, qa);
        qa = fmaf(-nq, PI2_LO, qa);
        float s8, c8;
        __sincosf(qa, &s8, &c8);
        sh_lr[tid] = lr;
        sh_r8[tid] = r8;
        sh_s8[tid] = s8;
        sh_c8[tid] = c8;
        sh_th[tid] = tk;
        sh_B[tid]  = -r8 * r8;
    }
    __syncthreads();

    // ---- stage 2: per-thread seeds; A and B packed in registers ----
    ull x1[NSLOT], x2[NSLOT], A[NSLOT], B[NSLOT];

    // seed exponents: e1 = seg*512 + tsub - 1 (first output), e2 = e1 - 8
    const float t2f = (float)(seg * SEG + tsub - 9);

    float p_x1 = 0.f, p_x2 = 0.f, p_A = 0.f, p_B = 0.f;

#pragma unroll
    for (int kk = 0; kk < KQ; ++kk) {
        const int k = kq * KQ + kk;
        float lr = sh_lr[k];
        float r8 = sh_r8[k];
        float s8 = sh_s8[k];
        float c8 = sh_c8[k];
        float tk = sh_th[k];
        float cB = sh_B[k];
        const int off = k * DD + d;
        float ar = __ldg(Rre + off);
        float ai = __ldg(Rim + off);

        float cA = 2.0f * r8 * c8;

        // seed x2 = x(e2): phase e2*th via exact twoProd + 2-term Cody-Waite
        float radm = __expf(t2f * lr);
        float ph = t2f * tk;
        float pe = fmaf(t2f, tk, -ph);      // exact low part of the product
        float n2 = rintf(ph * INV2PI);
        float a2 = fmaf(-n2, PI2_HI, ph);
        a2 = a2 + pe;
        a2 = fmaf(-n2, PI2_LO, a2);
        float sm, cm;
        __sincosf(a2, &sm, &cm);
        float cx2 = radm * (ar * cm - ai * sm);

        // seed x1 = x(e2+8): rotate phase by 8 th, scale radius by r^8
        float rad0 = radm * r8;
        float c0 = cm * c8 - sm * s8;
        float s0 = sm * c8 + cm * s8;
        float cx1 = rad0 * (ar * c0 - ai * s0);

        if (kk & 1) {
            x1[kk >> 1] = f2pack(p_x1, cx1);
            x2[kk >> 1] = f2pack(p_x2, cx2);
            A [kk >> 1] = f2pack(p_A,  cA);
            B [kk >> 1] = f2pack(p_B,  cB);
        } else {
            p_x1 = cx1; p_x2 = cx2; p_A = cA; p_B = cB;
        }
    }

    float* outp = out + (size_t)d * LLEN + seg * SEG + tsub;
    const bool do_store = (kq == 0);

    // 2-step unrolled main loop; x1/x2 swap roles (no register moves)
#pragma unroll 1
    for (int i = 0; i < STEPS; i += 2) {
        {
            float part = reduce4(x1);
            float s = part + __shfl_xor_sync(0xffffffffu, part, 8);
            s = s + __shfl_xor_sync(0xffffffffu, s, 16);
            if (do_store) outp[i * SREC] = s;
        }
#pragma unroll
        for (int s2 = 0; s2 < NSLOT; ++s2)
            x2[s2] = f2fma(A[s2], x1[s2], f2mul(B[s2], x2[s2]));
        {
            float part = reduce4(x2);
            float s = part + __shfl_xor_sync(0xffffffffu, part, 8);
            s = s + __shfl_xor_sync(0xffffffffu, s, 16);
            if (do_store) outp[(i + 1) * SREC] = s;
        }
#pragma unroll
        for (int s2 = 0; s2 < NSLOT; ++s2)
            x1[s2] = f2fma(A[s2], x2[s2], f2mul(B[s2], x1[s2]));
    }

    // l == 0 carries h_0; same thread (seg 0, lane 0) wrote l=0 above
    if (seg == 0 && lane == 0) {
        out[(size_t)d * LLEN] = __ldg(h0 + d);
    }
}

extern "C" void kernel_launch(void* const* d_in, const int* in_sizes, int n_in,
                              void* d_out, int out_size) {
    const float* rr  = (const float*)d_in[0];
    const float* th  = (const float*)d_in[1];
    const float* Rre = (const float*)d_in[2];
    const float* Rim = (const float*)d_in[3];
    const float* h0  = (const float*)d_in[4];
    float* out = (float*)d_out;
    modal_kernel<<<DD, 128>>>(rr, th, Rre, Rim, h0, out);
}